// round 11
// baseline (speedup 1.0000x reference)
#include <cuda_runtime.h>
#include <cuda_bf16.h>

// SimplePatchScorer: x (512,3,224,224) f32, W (1,768) f32, b (1,) f32
// out (512,196) f32.
//
// f = t*588 + e; t = i*16 + j; e = band*14 + wn (band = c*14+hn, 42 bands of
// 3584 contiguous floats = 896 float4). row = f/768, k = f mod 768.
//
// Data address for e (thread i, float4 group jp): float4 offset within image
//   band*896 + i*56 + wn*4 + jp      (patch cols are 16 floats = 4 float4)
// R8's bug: used band*224 and wn*1. Fixed here; structure unchanged:
//  (1) 384 threads/CTA: q in [0,6) sixths of 98 e-steps (7 whole bands),
//      i in [0,16), jp in [0,4). 512 CTAs x 12 warps -> ~41 warps/SM.
//  (2) __launch_bounds__(384,4) -> 42 regs, 4 CTAs/SM RF-exact.
//  (3) Periodic weight array W4[A] = W[A mod 768] (A < 2632): element m's
//      weight = W4s[swz(A + 588m)], single running index A.
//  (4) Band loop: inner 14 steps fully unrolled, immediate-offset LDG.128.
//  (5) __ldcs (read-once), swizzled weights, dual-accumulator predicated
//      FMA, <=8 shared atomics/thread.

#define BATCH    512
#define NROWS    196
#define KLEN     768
#define IMG_F4   37632           // 3*224*224/4
#define BAND_F4  896             // 3584 floats per band
#define W4LOG    2632            // max A = 864 + 1764 < 2632
#define W4PHYS   2720            // 2632 + 2632/32, rounded up
#define TPB      384

__global__ __launch_bounds__(TPB, 4)
void patch_scorer_kernel(const float* __restrict__ x,
                         const float* __restrict__ W,
                         const float* __restrict__ bias,
                         float* __restrict__ out)
{
    __shared__ float sW4[W4PHYS];    // sW4[A + (A>>5)] = W[A % 768]
    __shared__ float sAcc[200];      // 196 rows + pad for zero hi-flushes

    const int tid = threadIdx.x;
    const int b   = blockIdx.x;      // image

    for (int a = tid; a < W4LOG; a += TPB)
        sW4[a + (a >> 5)] = W[a % KLEN];
    if (tid < 200) sAcc[tid] = 0.0f;
    __syncthreads();

    const int q  = tid >> 6;         // e-sixth 0..5
    const int i  = (tid >> 2) & 15;  // patch row
    const int jp = tid & 3;          // float4 group (j = 4jp..4jp+3)

    const int tb = i * 16 + jp * 4;  // t of element m=0
    const int e0 = q * 98;

    // per-element start: f_m = (tb+m)*588 + e0
    const int f0 = tb * 588 + e0;
    const int R0 = f0 / KLEN;                       // rows for m=0..3
    const int R1 = (f0 +  588) / KLEN;
    const int R2 = (f0 + 1176) / KLEN;
    const int R3 = (f0 + 1764) / KLEN;
    const int A0s = f0 - R0 * KLEN;                 // kstart_0 in [0,768)
    const int s0 = KLEN - A0s;                      // steps before row wrap
    const int s1 = KLEN - ((f0 +  588) - R1 * KLEN);
    const int s2 = KLEN - ((f0 + 1176) - R2 * KLEN);
    const int s3 = KLEN - ((f0 + 1764) - R3 * KLEN);

    const float4* px = (const float4*)x + (size_t)b * IMG_F4 + i * 56 + jp;
    int off = q * 7 * BAND_F4;       // float4 offset of band 7q

    float l0 = 0.f, h0 = 0.f, l1 = 0.f, h1 = 0.f;
    float l2 = 0.f, h2 = 0.f, l3 = 0.f, h3 = 0.f;

    #pragma unroll 1
    for (int band = 0; band < 7; ++band) {
        const int nb = band * 14;
        #pragma unroll
        for (int u = 0; u < 14; ++u) {
            const float4 v = __ldcs(&px[off + 4 * u]);   // wn stride = 4 f4
            const int n = nb + u;
            const int A = A0s + n;

            const int i0 = A;          const float w0 = sW4[i0 + (i0 >> 5)];
            const int i1 = A + 588;    const float w1 = sW4[i1 + (i1 >> 5)];
            const int i2 = A + 1176;   const float w2 = sW4[i2 + (i2 >> 5)];
            const int i3 = A + 1764;   const float w3 = sW4[i3 + (i3 >> 5)];

            if (n < s0) l0 += v.x * w0; else h0 += v.x * w0;
            if (n < s1) l1 += v.y * w1; else h1 += v.y * w1;
            if (n < s2) l2 += v.z * w2; else h2 += v.z * w2;
            if (n < s3) l3 += v.w * w3; else h3 += v.w * w3;
        }
        off += BAND_F4;              // next band
    }

    atomicAdd(&sAcc[R0    ], l0);
    atomicAdd(&sAcc[R0 + 1], h0);
    atomicAdd(&sAcc[R1    ], l1);
    atomicAdd(&sAcc[R1 + 1], h1);
    atomicAdd(&sAcc[R2    ], l2);
    atomicAdd(&sAcc[R2 + 1], h2);
    atomicAdd(&sAcc[R3    ], l3);
    atomicAdd(&sAcc[R3 + 1], h3);

    __syncthreads();

    if (tid < NROWS)
        out[(size_t)b * NROWS + tid] = sAcc[tid] + bias[0];
}

extern "C" void kernel_launch(void* const* d_in, const int* in_sizes, int n_in,
                              void* d_out, int out_size)
{
    const float* x  = (const float*)d_in[0];   // (512,3,224,224)
    const float* W  = (const float*)d_in[1];   // (1,768)
    const float* bv = (const float*)d_in[2];   // (1,)
    float* out = (float*)d_out;                // (512,196)

    patch_scorer_kernel<<<BATCH, TPB>>>(x, W, bv, out);
}